// round 15
// baseline (speedup 1.0000x reference)
#include <cuda_runtime.h>
#include <cuda_bf16.h>
#include <math.h>
#include <stdint.h>

constexpr int LAY = 2, BS = 32, TS = 256, NS = 1024, MS = 1024, JS = 4096;

__device__ float g_G[(size_t)TS * BS * JS];       // layer-0 input gates
__device__ float g_G1[(size_t)TS * BS * JS];      // layer-1 input gates (helper-written)
__device__ __nv_bfloat16 g_hf[2][2][BS * MS];     // [pingpong][hi/lo] B-fragment-packed h
__device__ __nv_bfloat16 g_Wp[(size_t)LAY * 128 * 65536];  // A-fragment-packed Whh hi/lo
__device__ __nv_bfloat16 g_Af[(size_t)TS * BS * NS * 2];   // A-fragment-packed GEMM input hi/lo
__device__ __nv_bfloat16 g_Bf[(size_t)LAY * JS * NS * 2];  // B-fragment-packed Wih hi/lo
__device__ unsigned g_cnt;

// ---------------- helpers ----------------
__device__ __forceinline__ uint32_t smem_u32(const void* p) {
    uint32_t a;
    asm("{ .reg .u64 t; cvta.to.shared.u64 t, %1; cvt.u32.u64 %0, t; }" : "=r"(a) : "l"(p));
    return a;
}
#define CP16(saddr, gptr) \
    asm volatile("cp.async.cg.shared.global [%0], [%1], 16;" :: "r"(saddr), "l"(gptr))
#define CP_COMMIT() asm volatile("cp.async.commit_group;")
#define CP_WAIT2()  asm volatile("cp.async.wait_group 2;")
#define CP_WAIT1()  asm volatile("cp.async.wait_group 1;")
#define CP_WAIT0()  asm volatile("cp.async.wait_group 0;")

// D(16x8,f32) += A(16x16,bf16,row) * B(16x8,bf16,col)
#define MMA16816(d, a, b) \
    asm volatile("mma.sync.aligned.m16n8k16.row.col.f32.bf16.bf16.f32 " \
        "{%0,%1,%2,%3}, {%4,%5,%6,%7}, {%8,%9}, {%0,%1,%2,%3};" \
        : "+f"((d)[0]), "+f"((d)[1]), "+f"((d)[2]), "+f"((d)[3]) \
        : "r"((a).x), "r"((a).y), "r"((a).z), "r"((a).w), "r"((b).x), "r"((b).y))

// ---------------- one-time conversions ----------------
__global__ void conv_w_kernel(const float* __restrict__ Whh) {
    int idx = blockIdx.x * blockDim.x + threadIdx.x;
    int lane = idx & 31, mt = (idx >> 5) & 1, ks = (idx >> 6) & 63;
    int jt = (idx >> 12) & 127, l = idx >> 19;
    __nv_bfloat16 hi[8], lo[8];
    #pragma unroll
    for (int q = 0; q < 4; q++) {
        #pragma unroll
        for (int e = 0; e < 2; e++) {
            int rl = (lane >> 2) + (q & 1) * 8;
            int cl = (lane & 3) * 2 + (q >> 1) * 8 + e;
            int jr = mt * 16 + rl;
            int j = (jr >> 3) * 1024 + jt * 8 + (jr & 7);
            float v = Whh[((size_t)l * 4096 + j) * 1024 + ks * 16 + cl];
            __nv_bfloat16 h = __float2bfloat16(v);
            hi[q * 2 + e] = h;
            lo[q * 2 + e] = __float2bfloat16(v - __bfloat162float(h));
        }
    }
    size_t o = ((((size_t)(l * 128 + jt) * 64 + ks) * 2 + mt) * 2) * 256 + lane * 8;
    *(uint4*)&g_Wp[o]       = *(uint4*)hi;
    *(uint4*)&g_Wp[o + 256] = *(uint4*)lo;
}

__global__ void conv_a_kernel(const float* __restrict__ x) {
    int idx = blockIdx.x * blockDim.x + threadIdx.x;
    int lane = idx & 31, ks = (idx >> 5) & 63, rt = idx >> 11;
    __nv_bfloat16 hi[8], lo[8];
    #pragma unroll
    for (int q = 0; q < 4; q++) {
        #pragma unroll
        for (int e = 0; e < 2; e++) {
            int rl = (lane >> 2) + (q & 1) * 8;
            int cl = (lane & 3) * 2 + (q >> 1) * 8 + e;
            int row = rt * 16 + rl;
            int k = ks * 16 + cl;
            int tt = row >> 5, bb = row & 31;
            float v = x[((size_t)bb * 256 + tt) * 1024 + k];
            __nv_bfloat16 h = __float2bfloat16(v);
            hi[q * 2 + e] = h;
            lo[q * 2 + e] = __float2bfloat16(v - __bfloat162float(h));
        }
    }
    size_t o = (((size_t)rt * 64 + ks) * 2) * 256 + lane * 8;
    *(uint4*)&g_Af[o]       = *(uint4*)hi;
    *(uint4*)&g_Af[o + 256] = *(uint4*)lo;
}

__global__ void conv_b_kernel(const float* __restrict__ Wih) {
    int idx = blockIdx.x * blockDim.x + threadIdx.x;
    int lane = idx & 31, ks = (idx >> 5) & 63, ct = (idx >> 11) & 511, l = idx >> 20;
    int col = ct * 8 + (lane >> 2);
    __nv_bfloat16 hi[4], lo[4];
    #pragma unroll
    for (int s = 0; s < 4; s++) {
        int kl = (s >> 1) * 8 + (lane & 3) * 2 + (s & 1);
        float v = Wih[((size_t)l * 4096 + col) * 1024 + ks * 16 + kl];
        __nv_bfloat16 h = __float2bfloat16(v);
        hi[s] = h;
        lo[s] = __float2bfloat16(v - __bfloat162float(h));
    }
    size_t o = ((((size_t)(l * 512 + ct) * 64 + ks) * 2)) * 128 + lane * 4;
    *(uint2*)&g_Bf[o]       = *(uint2*)hi;
    *(uint2*)&g_Bf[o + 128] = *(uint2*)lo;
}

__global__ void init_hf_kernel(const float* __restrict__ h_l) {
    int i = blockIdx.x * blockDim.x + threadIdx.x;
    if (i == 0) g_cnt = 0u;
    if (i >= BS * MS) return;
    int b = i >> 10, m = i & 1023;
    float v = h_l[i];
    __nv_bfloat16 hv = __float2bfloat16(v);
    __nv_bfloat16 lv = __float2bfloat16(v - __bfloat162float(hv));
    int ks = m >> 4, kl = m & 15, nt = b >> 3;
    int ln = (b & 7) * 4 + ((kl & 7) >> 1);
    int slot = (kl >> 3) * 2 + (kl & 1);
    size_t o = ((size_t)(ks * 4 + nt) * 32 + ln) * 4 + slot;
    g_hf[0][0][o] = hv;
    g_hf[0][1][o] = lv;
}

// ---------------- HMMA input GEMM (layer 0 only now) ----------------
constexpr int GEMM_SMEM = 3 * 32768 + 512;

__global__ __launch_bounds__(256, 2)
void gemm_mma(int layer, const float* __restrict__ bih_l, const float* __restrict__ bhh_l) {
    extern __shared__ char sm[];
    uint32_t sb = smem_u32(sm);
    int tid = threadIdx.x, w = tid >> 5, lane = tid & 31;
    int bx = blockIdx.x, by = blockIdx.y;
    int wr = w >> 2, wc = w & 3;
    float* sBias = (float*)(sm + 3 * 32768);
    if (tid < 128) sBias[tid] = bih_l[bx * 128 + tid] + bhh_l[bx * 128 + tid];

    const size_t lB = (size_t)layer * 512;

    auto issueChunk = [&](int c) {
        uint32_t dst = sb + (uint32_t)(c % 3) * 32768;
        int ks0 = c * 2;
        #pragma unroll
        for (int i = 0; i < 4; i++) {
            int u = tid + i * 256;
            int rt = u >> 7, ks = (u >> 6) & 1, hl = (u >> 5) & 1, ln = u & 31;
            const char* src = (const char*)g_Af +
                ((((size_t)(by * 8 + rt)) * 64 + ks0 + ks) * 2 + hl) * 512 + ln * 16;
            CP16(dst + (uint32_t)u * 16, src);
        }
        #pragma unroll
        for (int i = 0; i < 4; i++) {
            int u = tid + i * 256;
            int ct = u >> 6, ks = (u >> 5) & 1, hl = (u >> 4) & 1, un = u & 15;
            const char* src = (const char*)g_Bf +
                (((lB + bx * 16 + ct) * 64 + ks0 + ks) * 2 + hl) * 256 + un * 16;
            CP16(dst + 16384 + (uint32_t)u * 16, src);
        }
        CP_COMMIT();
    };

    issueChunk(0);
    issueChunk(1);

    float acc[4][4][4];
    #pragma unroll
    for (int a = 0; a < 4; a++) for (int b = 0; b < 4; b++) for (int q = 0; q < 4; q++)
        acc[a][b][q] = 0.f;

    for (int c = 0; c < 32; c++) {
        if (c < 31) { CP_WAIT1(); } else { CP_WAIT0(); }
        __syncthreads();
        if (c < 30) issueChunk(c + 2);
        const char* bufA = sm + (c % 3) * 32768;
        const char* bufB = bufA + 16384;
        #pragma unroll
        for (int ks = 0; ks < 2; ks++) {
            uint4 aH[4], aL[4];
            #pragma unroll
            for (int mt = 0; mt < 4; mt++) {
                int rt = wr * 4 + mt;
                aH[mt] = *(const uint4*)(bufA + (((rt * 2 + ks) * 2 + 0) * 512) + lane * 16);
                aL[mt] = *(const uint4*)(bufA + (((rt * 2 + ks) * 2 + 1) * 512) + lane * 16);
            }
            #pragma unroll
            for (int nt = 0; nt < 4; nt++) {
                int ct = wc * 4 + nt;
                uint2 bH = *(const uint2*)(bufB + (((ct * 2 + ks) * 2 + 0) * 256) + lane * 8);
                uint2 bL = *(const uint2*)(bufB + (((ct * 2 + ks) * 2 + 1) * 256) + lane * 8);
                #pragma unroll
                for (int mt = 0; mt < 4; mt++) {
                    MMA16816(acc[mt][nt], aH[mt], bH);
                    MMA16816(acc[mt][nt], aH[mt], bL);
                    MMA16816(acc[mt][nt], aL[mt], bH);
                }
            }
        }
    }

    int r0 = by * 128 + wr * 64;
    int c0g = bx * 128 + wc * 32;
    #pragma unroll
    for (int mt = 0; mt < 4; mt++) {
        #pragma unroll
        for (int nt = 0; nt < 4; nt++) {
            int row = r0 + mt * 16 + (lane >> 2);
            int col = c0g + nt * 8 + (lane & 3) * 2;
            int lc = wc * 32 + nt * 8 + (lane & 3) * 2;
            float b0 = sBias[lc], b1 = sBias[lc + 1];
            float2 v0 = {acc[mt][nt][0] + b0, acc[mt][nt][1] + b1};
            float2 v1 = {acc[mt][nt][2] + b0, acc[mt][nt][3] + b1};
            *(float2*)&g_G[(size_t)row * 4096 + col] = v0;
            *(float2*)&g_G[(size_t)(row + 8) * 4096 + col] = v1;
        }
    }
}

// ---------------- persistent HMMA recurrence (R13 core) + G1 helper CTAs ----------------
// rec: 128 CTAs x 512 threads (R13 structure, untouched).
// helpers (layer-0 launch only, blockIdx 128..143): compute G1(t) = Af(2t,2t+1) @ Wih1 + bias
// as h0(t) is published, consuming the rec release counter.
constexpr int OFF_B = 131072, BCHUNK = 32768;
constexpr int OFF_P = 131072;              // overlay on h buffer 0
constexpr int REC_SMEM = 229376;
constexpr unsigned NREC = 128;

__global__ __launch_bounds__(512)
void rec_mma(const float* __restrict__ c_in_l, float* __restrict__ out_c_l,
             float* __restrict__ out_h_l, float* __restrict__ outs, int layer,
             const float* __restrict__ bih1, const float* __restrict__ bhh1) {
    extern __shared__ char sm[];
    int tid = threadIdx.x, w = tid >> 5, lane = tid & 31;
    uint32_t sb = smem_u32(sm);

    if (blockIdx.x >= 128) {
        // ================= G1 helper =================
        int hid = blockIdx.x - 128;
        float* sBias = (float*)sm;
        if (tid < 256) sBias[tid] = bih1[hid * 256 + tid] + bhh1[hid * 256 + tid];
        __syncthreads();
        int wr = w >> 3, wc = w & 7;

        for (int t = 0; t < TS; t++) {
            if (tid == 0) {  // wait for rec CTAs to publish g_Af rows of step t
                unsigned tgt = NREC * (unsigned)(t + 1);
                unsigned v;
                do {
                    asm volatile("ld.acquire.gpu.global.u32 %0, [%1];"
                                 : "=r"(v) : "l"(&g_cnt) : "memory");
                } while (v < tgt);
            }
            __syncthreads();

            // chunk c covers ks = 2c, 2c+1. buf at 4096 + (c&3)*36864: A 4KB | B 32KB
            auto issueHB = [&](int c) {
                uint32_t dst = sb + 4096 + (uint32_t)(c & 3) * 36864;
                int ks0 = c * 2;
                if (tid < 256) {   // A: 256 16B units
                    int sub = tid & 31, blk = tid >> 5;
                    int hl = blk & 1, ksl = (blk >> 1) & 1, rtl = blk >> 2;
                    const char* src = (const char*)g_Af +
                        (((size_t)(2 * t + rtl) * 64 + ks0 + ksl) * 2 + hl) * 512 + sub * 16;
                    CP16(dst + (uint32_t)tid * 16, src);
                }
                #pragma unroll
                for (int i = 0; i < 4; i++) {   // B: 2048 16B units
                    int u = tid + i * 512;
                    int sub = u & 15, blk = u >> 4;
                    int hl = blk & 1, ksl = (blk >> 1) & 1, ctl = blk >> 2;
                    const char* src = (const char*)g_Bf +
                        (((size_t)(512 + hid * 32 + ctl) * 64 + ks0 + ksl) * 2 + hl) * 256 + sub * 16;
                    CP16(dst + 4096 + (uint32_t)u * 16, src);
                }
                CP_COMMIT();
            };

            issueHB(0); issueHB(1); issueHB(2);

            float acc[4][4];
            #pragma unroll
            for (int n = 0; n < 4; n++) for (int q = 0; q < 4; q++) acc[n][q] = 0.f;

            for (int c = 0; c < 32; c++) {
                if (c <= 29) { CP_WAIT2(); } else if (c == 30) { CP_WAIT1(); } else { CP_WAIT0(); }
                __syncthreads();
                if (c + 3 < 32) issueHB(c + 3);
                uint32_t bufb = 4096u + (uint32_t)(c & 3) * 36864;
                #pragma unroll
                for (int ksl = 0; ksl < 2; ksl++) {
                    uint32_t ab = bufb + (uint32_t)((wr * 4 + ksl * 2) * 512);
                    uint4 aH = *(uint4*)(sm + ab + lane * 16);
                    uint4 aL = *(uint4*)(sm + ab + 512 + lane * 16);
                    #pragma unroll
                    for (int nt = 0; nt < 4; nt++) {
                        int ctl = wc * 4 + nt;
                        uint32_t bb = bufb + 4096 + (uint32_t)((ctl * 4 + ksl * 2) * 256);
                        uint2 bH = *(uint2*)(sm + bb + lane * 8);
                        uint2 bL = *(uint2*)(sm + bb + 256 + lane * 8);
                        MMA16816(acc[nt], aH, bH);
                        MMA16816(acc[nt], aH, bL);
                        MMA16816(acc[nt], aL, bH);
                    }
                }
            }

            int r0 = t * 32 + wr * 16 + (lane >> 2);
            #pragma unroll
            for (int nt = 0; nt < 4; nt++) {
                int lc = wc * 32 + nt * 8 + (lane & 3) * 2;
                int colg = hid * 256 + lc;
                float b0 = sBias[lc], b1 = sBias[lc + 1];
                float2 v0 = {acc[nt][0] + b0, acc[nt][1] + b1};
                float2 v1 = {acc[nt][2] + b0, acc[nt][3] + b1};
                *(float2*)&g_G1[(size_t)r0 * 4096 + colg] = v0;
                *(float2*)&g_G1[(size_t)(r0 + 8) * 4096 + colg] = v1;
            }
        }
        return;
    }

    // ================= rec CTA (R13 structure) =================
    int jt = blockIdx.x, m0 = jt * 8;
    const float* Gsrc = (layer == 0) ? g_G : g_G1;

    // preload W fragments (resident all timesteps)
    {
        const char* src = (const char*)g_Wp + (size_t)(layer * 128 + jt) * 131072;
        #pragma unroll
        for (int i = 0; i < 16; i++)
            CP16(sb + (uint32_t)(tid + i * 512) * 16, src + (size_t)(tid + i * 512) * 16);
        CP_COMMIT();
        CP_WAIT0();
    }
    __syncthreads();

    int eb = (tid >> 3) & 31, ml = tid & 7, m = m0 + ml;
    float creg = 0.f;
    if (tid < 256) creg = c_in_l[(size_t)eb * MS + m];

    for (int t = 0; t < TS; t++) {
        int pp = t & 1;
        const char* hH = (const char*)g_hf[pp][0];
        const char* hL = (const char*)g_hf[pp][1];

        float Gr[4];
        if (tid < 256) {
            #pragma unroll
            for (int g = 0; g < 4; g++)
                Gr[g] = __ldg(&Gsrc[((size_t)(t * 32 + eb)) * 4096 + g * 1024 + jt * 8 + ml]);
        }

        auto issueH = [&](int c, int buf) {
            uint32_t dst = sb + OFF_B + (uint32_t)buf * BCHUNK;
            const char* sh = hH + (size_t)c * 16384;
            const char* sl = hL + (size_t)c * 16384;
            #pragma unroll
            for (int i = 0; i < 2; i++) {
                uint32_t u16 = (uint32_t)(tid + i * 512) * 16;
                CP16(dst + u16, sh + u16);
                CP16(dst + 16384 + u16, sl + u16);
            }
            CP_COMMIT();
        };

        issueH(0, 0);
        issueH(1, 1);
        issueH(2, 2);

        float acc[2][4][4];
        #pragma unroll
        for (int a = 0; a < 2; a++) for (int n = 0; n < 4; n++) for (int q = 0; q < 4; q++)
            acc[a][n][q] = 0.f;

        #pragma unroll
        for (int c = 0; c < 4; c++) {
            if (c == 0)      { CP_WAIT2(); }
            else if (c == 1) { CP_WAIT1(); }
            else if (c == 2) { CP_WAIT1(); }
            else             { CP_WAIT0(); }
            __syncthreads();
            if (c == 1) issueH(3, 0);

            int ks = c * 16 + w;
            int buf = (c == 3) ? 0 : c;
            uint32_t abase = (uint32_t)(ks * 2048);
            uint4 aH0 = *(uint4*)(sm + abase +        lane * 16);
            uint4 aL0 = *(uint4*)(sm + abase + 512  + lane * 16);
            uint4 aH1 = *(uint4*)(sm + abase + 1024 + lane * 16);
            uint4 aL1 = *(uint4*)(sm + abase + 1536 + lane * 16);
            uint32_t bbase = (uint32_t)(OFF_B + buf * BCHUNK + w * 1024);
            #pragma unroll
            for (int nt = 0; nt < 4; nt++) {
                uint2 bH = *(uint2*)(sm + bbase + nt * 256 + lane * 8);
                uint2 bL = *(uint2*)(sm + bbase + 16384 + nt * 256 + lane * 8);
                MMA16816(acc[0][nt], aH0, bH);
                MMA16816(acc[0][nt], aH0, bL);
                MMA16816(acc[0][nt], aL0, bH);
                MMA16816(acc[1][nt], aH1, bH);
                MMA16816(acc[1][nt], aH1, bL);
                MMA16816(acc[1][nt], aL1, bH);
            }
        }
        __syncthreads();

        if (w < 8) {
            #pragma unroll
            for (int mt = 0; mt < 2; mt++)
                #pragma unroll
                for (int nt = 0; nt < 4; nt++) {
                    float4 v = {acc[mt][nt][0], acc[mt][nt][1], acc[mt][nt][2], acc[mt][nt][3]};
                    *(float4*)(sm + OFF_P + (((w * 2 + mt) * 4 + nt) * 32 + lane) * 16) = v;
                }
        }
        __syncthreads();
        if (w >= 8) {
            int ws = w - 8;
            #pragma unroll
            for (int mt = 0; mt < 2; mt++)
                #pragma unroll
                for (int nt = 0; nt < 4; nt++) {
                    float4* p = (float4*)(sm + OFF_P + (((ws * 2 + mt) * 4 + nt) * 32 + lane) * 16);
                    float4 v = *p;
                    v.x += acc[mt][nt][0]; v.y += acc[mt][nt][1];
                    v.z += acc[mt][nt][2]; v.w += acc[mt][nt][3];
                    *p = v;
                }
        }
        __syncthreads();

        if (tid < 256) {
            const float* sPf = (const float*)(sm + OFF_P);
            float gate[4];
            #pragma unroll
            for (int g = 0; g < 4; g++) {
                int jr = g * 8 + ml;
                int mt = jr >> 4, rl = jr & 15;
                int ln = (rl & 7) * 4 + ((eb & 7) >> 1);
                int rg = (rl >> 3) * 2 + (eb & 1);
                int nt = eb >> 3;
                float s = Gr[g];
                #pragma unroll
                for (int ww = 0; ww < 8; ww++)
                    s += sPf[(((ww * 2 + mt) * 4 + nt) * 32 + ln) * 4 + rg];
                gate[g] = s;
            }
            float i_ = 1.f / (1.f + __expf(-gate[0]));
            float f_ = 1.f / (1.f + __expf(-gate[1]));
            float g_ = tanhf(gate[2]);
            float o_ = 1.f / (1.f + __expf(-gate[3]));
            creg = f_ * creg + i_ * g_;
            float hn = o_ * tanhf(creg);

            __nv_bfloat16 hv = __float2bfloat16(hn);
            __nv_bfloat16 lv = __float2bfloat16(hn - __bfloat162float(hv));
            {
                int ks = m >> 4, kl = m & 15, nt = eb >> 3;
                int ln = (eb & 7) * 4 + ((kl & 7) >> 1);
                int slot = (kl >> 3) * 2 + (kl & 1);
                size_t o = ((size_t)(ks * 4 + nt) * 32 + ln) * 4 + slot;
                g_hf[pp ^ 1][0][o] = hv;
                g_hf[pp ^ 1][1][o] = lv;
            }
            if (layer == 0) {
                int rt = t * 2 + (eb >> 4);
                int rl = eb & 15;
                int ks2 = m >> 4, cl = m & 15;
                int lane2 = (rl & 7) * 4 + ((cl & 7) >> 1);
                int q2 = (rl >> 3) + ((cl >> 3) << 1);
                size_t oA = (((size_t)rt * 64 + ks2) * 2) * 256 + lane2 * 8 + q2 * 2 + (cl & 1);
                g_Af[oA]       = hv;
                g_Af[oA + 256] = lv;
            } else {
                outs[((size_t)eb * TS + t) * MS + m] = hn;
            }
            if (t == TS - 1) out_h_l[(size_t)eb * MS + m] = hn;
        }

        if (t < TS - 1) {
            __syncthreads();
            if (tid == 0) {
                unsigned tgt = (unsigned)(t + 1) * NREC;
                asm volatile("red.release.gpu.global.add.u32 [%0], %1;"
                             :: "l"(&g_cnt), "r"(1u) : "memory");
                unsigned v;
                do {
                    asm volatile("ld.acquire.gpu.global.u32 %0, [%1];"
                                 : "=r"(v) : "l"(&g_cnt) : "memory");
                } while (v < tgt);
            }
            __syncthreads();
        } else {
            __syncthreads();   // final release so helpers' t=TS-1 poll completes
            if (tid == 0)
                asm volatile("red.release.gpu.global.add.u32 [%0], %1;"
                             :: "l"(&g_cnt), "r"(1u) : "memory");
        }
    }
    if (tid < 256) out_c_l[(size_t)eb * MS + m] = creg;
}

// ------------------------------------------------------------------
extern "C" void kernel_launch(void* const* d_in, const int* in_sizes, int n_in,
                              void* d_out, int out_size) {
    const float* x   = (const float*)d_in[0];
    const float* h   = (const float*)d_in[1];
    const float* c   = (const float*)d_in[2];
    const float* Wih = (const float*)d_in[3];
    const float* Whh = (const float*)d_in[4];
    const float* bih = (const float*)d_in[5];
    const float* bhh = (const float*)d_in[6];

    float* outs  = (float*)d_out;
    float* out_h = outs + (size_t)BS * TS * MS;
    float* out_c = out_h + (size_t)LAY * BS * MS;

    cudaFuncSetAttribute(rec_mma, cudaFuncAttributeMaxDynamicSharedMemorySize, REC_SMEM);
    cudaFuncSetAttribute(gemm_mma, cudaFuncAttributeMaxDynamicSharedMemorySize, GEMM_SMEM);

    conv_w_kernel<<<4096, 256>>>(Whh);
    conv_b_kernel<<<8192, 256>>>(Wih);
    conv_a_kernel<<<4096, 256>>>(x);
    for (int l = 0; l < LAY; l++) {
        if (l == 0)
            gemm_mma<<<dim3(32, 64), 256, GEMM_SMEM>>>(l, bih, bhh);
        init_hf_kernel<<<(BS * MS + 255) / 256, 256>>>(h + (size_t)l * BS * MS);
        rec_mma<<<(l == 0 ? 144 : 128), 512, REC_SMEM>>>(
            c + (size_t)l * BS * MS,
            out_c + (size_t)l * BS * MS,
            out_h + (size_t)l * BS * MS,
            outs, l,
            bih + (size_t)JS, bhh + (size_t)JS);
    }
}

// round 16
// speedup vs baseline: 1.7190x; 1.7190x over previous
#include <cuda_runtime.h>
#include <cuda_bf16.h>
#include <math.h>
#include <stdint.h>

constexpr int LAY = 2, BS = 32, TS = 256, NS = 1024, MS = 1024, JS = 4096;

__device__ float g_G[(size_t)TS * BS * JS];       // input-gate precompute rows (t*32+b, j)
__device__ __nv_bfloat16 g_hf[2][2][BS * MS];     // [pingpong][hi/lo] B-fragment-packed h
__device__ __nv_bfloat16 g_Wp[(size_t)LAY * 128 * 65536];  // A-fragment-packed Whh hi/lo
__device__ __nv_bfloat16 g_Af[(size_t)TS * BS * NS * 2];   // A-fragment-packed GEMM input hi/lo
__device__ __nv_bfloat16 g_Bf[(size_t)LAY * JS * NS * 2];  // B-fragment-packed Wih hi/lo
__device__ unsigned g_cnt;

// ---------------- helpers ----------------
__device__ __forceinline__ uint32_t smem_u32(const void* p) {
    uint32_t a;
    asm("{ .reg .u64 t; cvta.to.shared.u64 t, %1; cvt.u32.u64 %0, t; }" : "=r"(a) : "l"(p));
    return a;
}
#define CP16(saddr, gptr) \
    asm volatile("cp.async.cg.shared.global [%0], [%1], 16;" :: "r"(saddr), "l"(gptr))
#define CP_COMMIT() asm volatile("cp.async.commit_group;")
#define CP_WAIT2()  asm volatile("cp.async.wait_group 2;")
#define CP_WAIT1()  asm volatile("cp.async.wait_group 1;")
#define CP_WAIT0()  asm volatile("cp.async.wait_group 0;")

// D(16x8,f32) += A(16x16,bf16,row) * B(16x8,bf16,col)
#define MMA16816(d, a, b) \
    asm volatile("mma.sync.aligned.m16n8k16.row.col.f32.bf16.bf16.f32 " \
        "{%0,%1,%2,%3}, {%4,%5,%6,%7}, {%8,%9}, {%0,%1,%2,%3};" \
        : "+f"((d)[0]), "+f"((d)[1]), "+f"((d)[2]), "+f"((d)[3]) \
        : "r"((a).x), "r"((a).y), "r"((a).z), "r"((a).w), "r"((b).x), "r"((b).y))

// ---------------- one-time conversions ----------------
// Whh -> per-CTA A-fragment pack (rec): [l][jt][ks][mt][hilo][lane][8 bf16]
__global__ void conv_w_kernel(const float* __restrict__ Whh) {
    int idx = blockIdx.x * blockDim.x + threadIdx.x;
    int lane = idx & 31, mt = (idx >> 5) & 1, ks = (idx >> 6) & 63;
    int jt = (idx >> 12) & 127, l = idx >> 19;
    __nv_bfloat16 hi[8], lo[8];
    #pragma unroll
    for (int q = 0; q < 4; q++) {
        #pragma unroll
        for (int e = 0; e < 2; e++) {
            int rl = (lane >> 2) + (q & 1) * 8;
            int cl = (lane & 3) * 2 + (q >> 1) * 8 + e;
            int jr = mt * 16 + rl;
            int j = (jr >> 3) * 1024 + jt * 8 + (jr & 7);
            float v = Whh[((size_t)l * 4096 + j) * 1024 + ks * 16 + cl];
            __nv_bfloat16 h = __float2bfloat16(v);
            hi[q * 2 + e] = h;
            lo[q * 2 + e] = __float2bfloat16(v - __bfloat162float(h));
        }
    }
    size_t o = ((((size_t)(l * 128 + jt) * 64 + ks) * 2 + mt) * 2) * 256 + lane * 8;
    *(uint4*)&g_Wp[o]       = *(uint4*)hi;
    *(uint4*)&g_Wp[o + 256] = *(uint4*)lo;
}

// GEMM A pack for layer 0 (from x). Layer 1's pack is written by rec_mma directly.
__global__ void conv_a_kernel(const float* __restrict__ x) {
    int idx = blockIdx.x * blockDim.x + threadIdx.x;   // 1,048,576
    int lane = idx & 31, ks = (idx >> 5) & 63, rt = idx >> 11;
    __nv_bfloat16 hi[8], lo[8];
    #pragma unroll
    for (int q = 0; q < 4; q++) {
        #pragma unroll
        for (int e = 0; e < 2; e++) {
            int rl = (lane >> 2) + (q & 1) * 8;
            int cl = (lane & 3) * 2 + (q >> 1) * 8 + e;
            int row = rt * 16 + rl;
            int k = ks * 16 + cl;
            int tt = row >> 5, bb = row & 31;
            float v = x[((size_t)bb * 256 + tt) * 1024 + k];
            __nv_bfloat16 h = __float2bfloat16(v);
            hi[q * 2 + e] = h;
            lo[q * 2 + e] = __float2bfloat16(v - __bfloat162float(h));
        }
    }
    size_t o = (((size_t)rt * 64 + ks) * 2) * 256 + lane * 8;
    *(uint4*)&g_Af[o]       = *(uint4*)hi;
    *(uint4*)&g_Af[o + 256] = *(uint4*)lo;
}

// GEMM B pack (Wih, both layers): [l][ct 512][ks 64][hilo][lane][4 bf16]
__global__ void conv_b_kernel(const float* __restrict__ Wih) {
    int idx = blockIdx.x * blockDim.x + threadIdx.x;   // 2,097,152
    int lane = idx & 31, ks = (idx >> 5) & 63, ct = (idx >> 11) & 511, l = idx >> 20;
    int col = ct * 8 + (lane >> 2);
    __nv_bfloat16 hi[4], lo[4];
    #pragma unroll
    for (int s = 0; s < 4; s++) {
        int kl = (s >> 1) * 8 + (lane & 3) * 2 + (s & 1);
        float v = Wih[((size_t)l * 4096 + col) * 1024 + ks * 16 + kl];
        __nv_bfloat16 h = __float2bfloat16(v);
        hi[s] = h;
        lo[s] = __float2bfloat16(v - __bfloat162float(h));
    }
    size_t o = ((((size_t)(l * 512 + ct) * 64 + ks) * 2)) * 128 + lane * 4;
    *(uint2*)&g_Bf[o]       = *(uint2*)hi;
    *(uint2*)&g_Bf[o + 128] = *(uint2*)lo;
}

// initial h -> B-fragment pack (pingpong 0); reset barrier counter
__global__ void init_hf_kernel(const float* __restrict__ h_l) {
    int i = blockIdx.x * blockDim.x + threadIdx.x;
    if (i == 0) g_cnt = 0u;
    if (i >= BS * MS) return;
    int b = i >> 10, m = i & 1023;
    float v = h_l[i];
    __nv_bfloat16 hv = __float2bfloat16(v);
    __nv_bfloat16 lv = __float2bfloat16(v - __bfloat162float(hv));
    int ks = m >> 4, kl = m & 15, nt = b >> 3;
    int ln = (b & 7) * 4 + ((kl & 7) >> 1);
    int slot = (kl >> 3) * 2 + (kl & 1);
    size_t o = ((size_t)(ks * 4 + nt) * 32 + ln) * 4 + slot;
    g_hf[0][0][o] = hv;
    g_hf[0][1][o] = lv;
}

// ---------------- HMMA input GEMM (proven: K=32 chunks, 2 CTAs/SM) ----------------
constexpr int GEMM_SMEM = 3 * 32768 + 512;

__global__ __launch_bounds__(256, 2)
void gemm_mma(int layer, const float* __restrict__ bih_l, const float* __restrict__ bhh_l) {
    extern __shared__ char sm[];
    uint32_t sb = smem_u32(sm);
    int tid = threadIdx.x, w = tid >> 5, lane = tid & 31;
    int bx = blockIdx.x, by = blockIdx.y;
    int wr = w >> 2, wc = w & 3;
    float* sBias = (float*)(sm + 3 * 32768);
    if (tid < 128) sBias[tid] = bih_l[bx * 128 + tid] + bhh_l[bx * 128 + tid];

    const size_t lB = (size_t)layer * 512;

    auto issueChunk = [&](int c) {
        uint32_t dst = sb + (uint32_t)(c % 3) * 32768;
        int ks0 = c * 2;
        #pragma unroll
        for (int i = 0; i < 4; i++) {
            int u = tid + i * 256;
            int rt = u >> 7, ks = (u >> 6) & 1, hl = (u >> 5) & 1, ln = u & 31;
            const char* src = (const char*)g_Af +
                ((((size_t)(by * 8 + rt)) * 64 + ks0 + ks) * 2 + hl) * 512 + ln * 16;
            CP16(dst + (uint32_t)u * 16, src);
        }
        #pragma unroll
        for (int i = 0; i < 4; i++) {
            int u = tid + i * 256;
            int ct = u >> 6, ks = (u >> 5) & 1, hl = (u >> 4) & 1, un = u & 15;
            const char* src = (const char*)g_Bf +
                (((lB + bx * 16 + ct) * 64 + ks0 + ks) * 2 + hl) * 256 + un * 16;
            CP16(dst + 16384 + (uint32_t)u * 16, src);
        }
        CP_COMMIT();
    };

    issueChunk(0);
    issueChunk(1);

    float acc[4][4][4];
    #pragma unroll
    for (int a = 0; a < 4; a++) for (int b = 0; b < 4; b++) for (int q = 0; q < 4; q++)
        acc[a][b][q] = 0.f;

    for (int c = 0; c < 32; c++) {
        if (c < 31) { CP_WAIT1(); } else { CP_WAIT0(); }
        __syncthreads();
        if (c < 30) issueChunk(c + 2);
        const char* bufA = sm + (c % 3) * 32768;
        const char* bufB = bufA + 16384;
        #pragma unroll
        for (int ks = 0; ks < 2; ks++) {
            uint4 aH[4], aL[4];
            #pragma unroll
            for (int mt = 0; mt < 4; mt++) {
                int rt = wr * 4 + mt;
                aH[mt] = *(const uint4*)(bufA + (((rt * 2 + ks) * 2 + 0) * 512) + lane * 16);
                aL[mt] = *(const uint4*)(bufA + (((rt * 2 + ks) * 2 + 1) * 512) + lane * 16);
            }
            #pragma unroll
            for (int nt = 0; nt < 4; nt++) {
                int ct = wc * 4 + nt;
                uint2 bH = *(const uint2*)(bufB + (((ct * 2 + ks) * 2 + 0) * 256) + lane * 8);
                uint2 bL = *(const uint2*)(bufB + (((ct * 2 + ks) * 2 + 1) * 256) + lane * 8);
                #pragma unroll
                for (int mt = 0; mt < 4; mt++) {
                    MMA16816(acc[mt][nt], aH[mt], bH);
                    MMA16816(acc[mt][nt], aH[mt], bL);
                    MMA16816(acc[mt][nt], aL[mt], bH);
                }
            }
        }
    }

    int r0 = by * 128 + wr * 64;
    int c0g = bx * 128 + wc * 32;
    #pragma unroll
    for (int mt = 0; mt < 4; mt++) {
        #pragma unroll
        for (int nt = 0; nt < 4; nt++) {
            int row = r0 + mt * 16 + (lane >> 2);
            int col = c0g + nt * 8 + (lane & 3) * 2;
            int lc = wc * 32 + nt * 8 + (lane & 3) * 2;
            float b0 = sBias[lc], b1 = sBias[lc + 1];
            float2 v0 = {acc[mt][nt][0] + b0, acc[mt][nt][1] + b1};
            float2 v1 = {acc[mt][nt][2] + b0, acc[mt][nt][3] + b1};
            *(float2*)&g_G[(size_t)row * 4096 + col] = v0;
            *(float2*)&g_G[(size_t)(row + 8) * 4096 + col] = v1;
        }
    }
}

// ---------------- persistent HMMA recurrence (R13 core + per-warp barrier poll) ----------------
// 128 CTAs x 512 threads. W resident 128KB. h: 3 x 32KB buffers (chunks 0,1,2
// up front; chunk 3 reuses buf 0). Partials overlay buf 0.
// Barrier: pre-release syncthreads + tid0 release (R13); the WAIT is a per-warp
// lane-0 acquire poll at the top of the next step (removes one CTA-wide
// syncthreads and the single-poller convoy).
constexpr int OFF_B = 131072, BCHUNK = 32768;
constexpr int OFF_P = 131072;              // overlay on h buffer 0
constexpr int REC_SMEM = 229376;

__global__ __launch_bounds__(512)
void rec_mma(const float* __restrict__ c_in_l, float* __restrict__ out_c_l,
             float* __restrict__ out_h_l, float* __restrict__ outs, int layer) {
    extern __shared__ char sm[];
    int tid = threadIdx.x, w = tid >> 5, lane = tid & 31;
    int jt = blockIdx.x, m0 = jt * 8;
    uint32_t sb = smem_u32(sm);

    // preload W fragments (resident all timesteps)
    {
        const char* src = (const char*)g_Wp + (size_t)(layer * 128 + jt) * 131072;
        #pragma unroll
        for (int i = 0; i < 16; i++)
            CP16(sb + (uint32_t)(tid + i * 512) * 16, src + (size_t)(tid + i * 512) * 16);
        CP_COMMIT();
        CP_WAIT0();
    }
    __syncthreads();

    int eb = (tid >> 3) & 31, ml = tid & 7, m = m0 + ml;
    float creg = 0.f;
    if (tid < 256) creg = c_in_l[(size_t)eb * MS + m];

    for (int t = 0; t < TS; t++) {
        int pp = t & 1;

        // per-warp wait for h(t): lane 0 polls with acquire, warp proceeds on flip
        if (t > 0) {
            if (lane == 0) {
                unsigned tgt = (unsigned)t * gridDim.x;
                unsigned v;
                do {
                    asm volatile("ld.acquire.gpu.global.u32 %0, [%1];"
                                 : "=r"(v) : "l"(&g_cnt) : "memory");
                } while (v < tgt);
            }
            __syncwarp();
        }

        const char* hH = (const char*)g_hf[pp][0];
        const char* hL = (const char*)g_hf[pp][1];

        // G prefetch into registers (read-only during rec; hidden by chunk loop)
        float Gr[4];
        if (tid < 256) {
            #pragma unroll
            for (int g = 0; g < 4; g++)
                Gr[g] = __ldg(&g_G[((size_t)(t * 32 + eb)) * 4096 + g * 1024 + jt * 8 + ml]);
        }

        auto issueH = [&](int c, int buf) {
            uint32_t dst = sb + OFF_B + (uint32_t)buf * BCHUNK;
            const char* sh = hH + (size_t)c * 16384;
            const char* sl = hL + (size_t)c * 16384;
            #pragma unroll
            for (int i = 0; i < 2; i++) {
                uint32_t u16 = (uint32_t)(tid + i * 512) * 16;
                CP16(dst + u16, sh + u16);
                CP16(dst + 16384 + u16, sl + u16);
            }
            CP_COMMIT();
        };

        // all of h(t) is available: issue chunks 0,1,2 up front
        issueH(0, 0);
        issueH(1, 1);
        issueH(2, 2);

        float acc[2][4][4];
        #pragma unroll
        for (int a = 0; a < 2; a++) for (int n = 0; n < 4; n++) for (int q = 0; q < 4; q++)
            acc[a][n][q] = 0.f;

        #pragma unroll
        for (int c = 0; c < 4; c++) {
            if (c == 0)      { CP_WAIT2(); }
            else if (c == 1) { CP_WAIT1(); }
            else if (c == 2) { CP_WAIT1(); }
            else             { CP_WAIT0(); }
            __syncthreads();                   // all threads' chunk-c copies visible
            if (c == 1) issueH(3, 0);          // buf0 free: all threads past chunk0

            int ks = c * 16 + w;
            int buf = (c == 3) ? 0 : c;
            uint32_t abase = (uint32_t)(ks * 2048);
            uint4 aH0 = *(uint4*)(sm + abase +        lane * 16);
            uint4 aL0 = *(uint4*)(sm + abase + 512  + lane * 16);
            uint4 aH1 = *(uint4*)(sm + abase + 1024 + lane * 16);
            uint4 aL1 = *(uint4*)(sm + abase + 1536 + lane * 16);
            uint32_t bbase = (uint32_t)(OFF_B + buf * BCHUNK + w * 1024);
            #pragma unroll
            for (int nt = 0; nt < 4; nt++) {
                uint2 bH = *(uint2*)(sm + bbase + nt * 256 + lane * 8);
                uint2 bL = *(uint2*)(sm + bbase + 16384 + nt * 256 + lane * 8);
                MMA16816(acc[0][nt], aH0, bH);
                MMA16816(acc[0][nt], aH0, bL);
                MMA16816(acc[0][nt], aL0, bH);
                MMA16816(acc[1][nt], aH1, bH);
                MMA16816(acc[1][nt], aH1, bL);
                MMA16816(acc[1][nt], aL1, bH);
            }
        }
        __syncthreads();   // all warps done reading buf0 before partials overlay it

        // two-phase partial staging (overlaid on h buffer 0)
        if (w < 8) {
            #pragma unroll
            for (int mt = 0; mt < 2; mt++)
                #pragma unroll
                for (int nt = 0; nt < 4; nt++) {
                    float4 v = {acc[mt][nt][0], acc[mt][nt][1], acc[mt][nt][2], acc[mt][nt][3]};
                    *(float4*)(sm + OFF_P + (((w * 2 + mt) * 4 + nt) * 32 + lane) * 16) = v;
                }
        }
        __syncthreads();
        if (w >= 8) {
            int ws = w - 8;
            #pragma unroll
            for (int mt = 0; mt < 2; mt++)
                #pragma unroll
                for (int nt = 0; nt < 4; nt++) {
                    float4* p = (float4*)(sm + OFF_P + (((ws * 2 + mt) * 4 + nt) * 32 + lane) * 16);
                    float4 v = *p;
                    v.x += acc[mt][nt][0]; v.y += acc[mt][nt][1];
                    v.z += acc[mt][nt][2]; v.w += acc[mt][nt][3];
                    *p = v;
                }
        }
        __syncthreads();

        if (tid < 256) {
            const float* sPf = (const float*)(sm + OFF_P);
            float gate[4];
            #pragma unroll
            for (int g = 0; g < 4; g++) {
                int jr = g * 8 + ml;
                int mt = jr >> 4, rl = jr & 15;
                int ln = (rl & 7) * 4 + ((eb & 7) >> 1);
                int rg = (rl >> 3) * 2 + (eb & 1);
                int nt = eb >> 3;
                float s = Gr[g];
                #pragma unroll
                for (int ww = 0; ww < 8; ww++)
                    s += sPf[(((ww * 2 + mt) * 4 + nt) * 32 + ln) * 4 + rg];
                gate[g] = s;
            }
            float i_ = 1.f / (1.f + __expf(-gate[0]));
            float f_ = 1.f / (1.f + __expf(-gate[1]));
            float g_ = tanhf(gate[2]);
            float o_ = 1.f / (1.f + __expf(-gate[3]));
            creg = f_ * creg + i_ * g_;
            float hn = o_ * tanhf(creg);

            __nv_bfloat16 hv = __float2bfloat16(hn);
            __nv_bfloat16 lv = __float2bfloat16(hn - __bfloat162float(hv));
            // B-fragment pack for next step
            {
                int ks = m >> 4, kl = m & 15, nt = eb >> 3;
                int ln = (eb & 7) * 4 + ((kl & 7) >> 1);
                int slot = (kl >> 3) * 2 + (kl & 1);
                size_t o = ((size_t)(ks * 4 + nt) * 32 + ln) * 4 + slot;
                g_hf[pp ^ 1][0][o] = hv;
                g_hf[pp ^ 1][1][o] = lv;
            }
            if (layer == 0) {
                // A-fragment pack directly (layer-1 GEMM input)
                int rt = t * 2 + (eb >> 4);
                int rl = eb & 15;
                int ks2 = m >> 4, cl = m & 15;
                int lane2 = (rl & 7) * 4 + ((cl & 7) >> 1);
                int q2 = (rl >> 3) + ((cl >> 3) << 1);
                size_t oA = (((size_t)rt * 64 + ks2) * 2) * 256 + lane2 * 8 + q2 * 2 + (cl & 1);
                g_Af[oA]       = hv;
                g_Af[oA + 256] = lv;
            } else {
                outs[((size_t)eb * TS + t) * MS + m] = hn;
            }
            if (t == TS - 1) out_h_l[(size_t)eb * MS + m] = hn;
        }

        if (t < TS - 1) {
            __syncthreads();   // g_hf stores complete CTA-wide before release
            if (tid == 0)
                asm volatile("red.release.gpu.global.add.u32 [%0], %1;"
                             :: "l"(&g_cnt), "r"(1u) : "memory");
        }
    }
    if (tid < 256) out_c_l[(size_t)eb * MS + m] = creg;
}

// ------------------------------------------------------------------
extern "C" void kernel_launch(void* const* d_in, const int* in_sizes, int n_in,
                              void* d_out, int out_size) {
    const float* x   = (const float*)d_in[0];
    const float* h   = (const float*)d_in[1];
    const float* c   = (const float*)d_in[2];
    const float* Wih = (const float*)d_in[3];
    const float* Whh = (const float*)d_in[4];
    const float* bih = (const float*)d_in[5];
    const float* bhh = (const float*)d_in[6];

    float* outs  = (float*)d_out;
    float* out_h = outs + (size_t)BS * TS * MS;
    float* out_c = out_h + (size_t)LAY * BS * MS;

    cudaFuncSetAttribute(rec_mma, cudaFuncAttributeMaxDynamicSharedMemorySize, REC_SMEM);
    cudaFuncSetAttribute(gemm_mma, cudaFuncAttributeMaxDynamicSharedMemorySize, GEMM_SMEM);

    conv_w_kernel<<<4096, 256>>>(Whh);
    conv_b_kernel<<<8192, 256>>>(Wih);
    conv_a_kernel<<<4096, 256>>>(x);
    for (int l = 0; l < LAY; l++) {
        gemm_mma<<<dim3(32, 64), 256, GEMM_SMEM>>>(
            l, bih + (size_t)l * JS, bhh + (size_t)l * JS);
        init_hf_kernel<<<(BS * MS + 255) / 256, 256>>>(h + (size_t)l * BS * MS);
        rec_mma<<<128, 512, REC_SMEM>>>(
            c + (size_t)l * BS * MS,
            out_c + (size_t)l * BS * MS,
            out_h + (size_t)l * BS * MS,
            outs, l);
    }
}

// round 17
// speedup vs baseline: 2.2077x; 1.2843x over previous
#include <cuda_runtime.h>
#include <cuda_bf16.h>
#include <math.h>
#include <stdint.h>

constexpr int LAY = 2, BS = 32, TS = 256, NS = 1024, MS = 1024, JS = 4096;

__device__ float g_G[(size_t)TS * BS * JS];       // input-gate precompute rows (t*32+b, j)
__device__ __nv_bfloat16 g_hf[2][2][BS * MS];     // [pingpong][hi/lo] B-fragment-packed h
__device__ __nv_bfloat16 g_Wp[(size_t)LAY * 128 * 65536];  // A-fragment-packed Whh hi/lo
__device__ __nv_bfloat16 g_Af[(size_t)TS * BS * NS * 2];   // A-fragment-packed GEMM input hi/lo
__device__ __nv_bfloat16 g_Bf[(size_t)LAY * JS * NS * 2];  // B-fragment-packed Wih hi/lo
__device__ unsigned g_cnt;

// ---------------- helpers ----------------
__device__ __forceinline__ uint32_t smem_u32(const void* p) {
    uint32_t a;
    asm("{ .reg .u64 t; cvta.to.shared.u64 t, %1; cvt.u32.u64 %0, t; }" : "=r"(a) : "l"(p));
    return a;
}
#define CP16(saddr, gptr) \
    asm volatile("cp.async.cg.shared.global [%0], [%1], 16;" :: "r"(saddr), "l"(gptr))
#define CP_COMMIT() asm volatile("cp.async.commit_group;")
#define CP_WAIT2()  asm volatile("cp.async.wait_group 2;")
#define CP_WAIT1()  asm volatile("cp.async.wait_group 1;")
#define CP_WAIT0()  asm volatile("cp.async.wait_group 0;")

// D(16x8,f32) += A(16x16,bf16,row) * B(16x8,bf16,col)
#define MMA16816(d, a, b) \
    asm volatile("mma.sync.aligned.m16n8k16.row.col.f32.bf16.bf16.f32 " \
        "{%0,%1,%2,%3}, {%4,%5,%6,%7}, {%8,%9}, {%0,%1,%2,%3};" \
        : "+f"((d)[0]), "+f"((d)[1]), "+f"((d)[2]), "+f"((d)[3]) \
        : "r"((a).x), "r"((a).y), "r"((a).z), "r"((a).w), "r"((b).x), "r"((b).y))

// ---------------- one-time conversions ----------------
// Whh -> per-CTA A-fragment pack (rec): [l][jt][ks][mt][hilo][lane][8 bf16]
__global__ void conv_w_kernel(const float* __restrict__ Whh) {
    int idx = blockIdx.x * blockDim.x + threadIdx.x;
    int lane = idx & 31, mt = (idx >> 5) & 1, ks = (idx >> 6) & 63;
    int jt = (idx >> 12) & 127, l = idx >> 19;
    __nv_bfloat16 hi[8], lo[8];
    #pragma unroll
    for (int q = 0; q < 4; q++) {
        #pragma unroll
        for (int e = 0; e < 2; e++) {
            int rl = (lane >> 2) + (q & 1) * 8;
            int cl = (lane & 3) * 2 + (q >> 1) * 8 + e;
            int jr = mt * 16 + rl;
            int j = (jr >> 3) * 1024 + jt * 8 + (jr & 7);
            float v = Whh[((size_t)l * 4096 + j) * 1024 + ks * 16 + cl];
            __nv_bfloat16 h = __float2bfloat16(v);
            hi[q * 2 + e] = h;
            lo[q * 2 + e] = __float2bfloat16(v - __bfloat162float(h));
        }
    }
    size_t o = ((((size_t)(l * 128 + jt) * 64 + ks) * 2 + mt) * 2) * 256 + lane * 8;
    *(uint4*)&g_Wp[o]       = *(uint4*)hi;
    *(uint4*)&g_Wp[o + 256] = *(uint4*)lo;
}

// GEMM A pack for layer 0 (from x). Layer 1's pack is written by rec_mma directly.
__global__ void conv_a_kernel(const float* __restrict__ x) {
    int idx = blockIdx.x * blockDim.x + threadIdx.x;   // 1,048,576
    int lane = idx & 31, ks = (idx >> 5) & 63, rt = idx >> 11;
    __nv_bfloat16 hi[8], lo[8];
    #pragma unroll
    for (int q = 0; q < 4; q++) {
        #pragma unroll
        for (int e = 0; e < 2; e++) {
            int rl = (lane >> 2) + (q & 1) * 8;
            int cl = (lane & 3) * 2 + (q >> 1) * 8 + e;
            int row = rt * 16 + rl;
            int k = ks * 16 + cl;
            int tt = row >> 5, bb = row & 31;
            float v = x[((size_t)bb * 256 + tt) * 1024 + k];
            __nv_bfloat16 h = __float2bfloat16(v);
            hi[q * 2 + e] = h;
            lo[q * 2 + e] = __float2bfloat16(v - __bfloat162float(h));
        }
    }
    size_t o = (((size_t)rt * 64 + ks) * 2) * 256 + lane * 8;
    *(uint4*)&g_Af[o]       = *(uint4*)hi;
    *(uint4*)&g_Af[o + 256] = *(uint4*)lo;
}

// GEMM B pack (Wih, both layers): [l][ct 512][ks 64][hilo][lane][4 bf16]
__global__ void conv_b_kernel(const float* __restrict__ Wih) {
    int idx = blockIdx.x * blockDim.x + threadIdx.x;   // 2,097,152
    int lane = idx & 31, ks = (idx >> 5) & 63, ct = (idx >> 11) & 511, l = idx >> 20;
    int col = ct * 8 + (lane >> 2);
    __nv_bfloat16 hi[4], lo[4];
    #pragma unroll
    for (int s = 0; s < 4; s++) {
        int kl = (s >> 1) * 8 + (lane & 3) * 2 + (s & 1);
        float v = Wih[((size_t)l * 4096 + col) * 1024 + ks * 16 + kl];
        __nv_bfloat16 h = __float2bfloat16(v);
        hi[s] = h;
        lo[s] = __float2bfloat16(v - __bfloat162float(h));
    }
    size_t o = ((((size_t)(l * 512 + ct) * 64 + ks) * 2)) * 128 + lane * 4;
    *(uint2*)&g_Bf[o]       = *(uint2*)hi;
    *(uint2*)&g_Bf[o + 128] = *(uint2*)lo;
}

// initial h -> B-fragment pack (pingpong 0); reset barrier counter
__global__ void init_hf_kernel(const float* __restrict__ h_l) {
    int i = blockIdx.x * blockDim.x + threadIdx.x;
    if (i == 0) g_cnt = 0u;
    if (i >= BS * MS) return;
    int b = i >> 10, m = i & 1023;
    float v = h_l[i];
    __nv_bfloat16 hv = __float2bfloat16(v);
    __nv_bfloat16 lv = __float2bfloat16(v - __bfloat162float(hv));
    int ks = m >> 4, kl = m & 15, nt = b >> 3;
    int ln = (b & 7) * 4 + ((kl & 7) >> 1);
    int slot = (kl >> 3) * 2 + (kl & 1);
    size_t o = ((size_t)(ks * 4 + nt) * 32 + ln) * 4 + slot;
    g_hf[0][0][o] = hv;
    g_hf[0][1][o] = lv;
}

// ---------------- HMMA input GEMM (proven: K=32 chunks, 2 CTAs/SM) ----------------
constexpr int GEMM_SMEM = 3 * 32768 + 512;

__global__ __launch_bounds__(256, 2)
void gemm_mma(int layer, const float* __restrict__ bih_l, const float* __restrict__ bhh_l) {
    extern __shared__ char sm[];
    uint32_t sb = smem_u32(sm);
    int tid = threadIdx.x, w = tid >> 5, lane = tid & 31;
    int bx = blockIdx.x, by = blockIdx.y;
    int wr = w >> 2, wc = w & 3;
    float* sBias = (float*)(sm + 3 * 32768);
    if (tid < 128) sBias[tid] = bih_l[bx * 128 + tid] + bhh_l[bx * 128 + tid];

    const size_t lB = (size_t)layer * 512;

    auto issueChunk = [&](int c) {
        uint32_t dst = sb + (uint32_t)(c % 3) * 32768;
        int ks0 = c * 2;
        #pragma unroll
        for (int i = 0; i < 4; i++) {
            int u = tid + i * 256;
            int rt = u >> 7, ks = (u >> 6) & 1, hl = (u >> 5) & 1, ln = u & 31;
            const char* src = (const char*)g_Af +
                ((((size_t)(by * 8 + rt)) * 64 + ks0 + ks) * 2 + hl) * 512 + ln * 16;
            CP16(dst + (uint32_t)u * 16, src);
        }
        #pragma unroll
        for (int i = 0; i < 4; i++) {
            int u = tid + i * 256;
            int ct = u >> 6, ks = (u >> 5) & 1, hl = (u >> 4) & 1, un = u & 15;
            const char* src = (const char*)g_Bf +
                (((lB + bx * 16 + ct) * 64 + ks0 + ks) * 2 + hl) * 256 + un * 16;
            CP16(dst + 16384 + (uint32_t)u * 16, src);
        }
        CP_COMMIT();
    };

    issueChunk(0);
    issueChunk(1);

    float acc[4][4][4];
    #pragma unroll
    for (int a = 0; a < 4; a++) for (int b = 0; b < 4; b++) for (int q = 0; q < 4; q++)
        acc[a][b][q] = 0.f;

    for (int c = 0; c < 32; c++) {
        if (c < 31) { CP_WAIT1(); } else { CP_WAIT0(); }
        __syncthreads();
        if (c < 30) issueChunk(c + 2);
        const char* bufA = sm + (c % 3) * 32768;
        const char* bufB = bufA + 16384;
        #pragma unroll
        for (int ks = 0; ks < 2; ks++) {
            uint4 aH[4], aL[4];
            #pragma unroll
            for (int mt = 0; mt < 4; mt++) {
                int rt = wr * 4 + mt;
                aH[mt] = *(const uint4*)(bufA + (((rt * 2 + ks) * 2 + 0) * 512) + lane * 16);
                aL[mt] = *(const uint4*)(bufA + (((rt * 2 + ks) * 2 + 1) * 512) + lane * 16);
            }
            #pragma unroll
            for (int nt = 0; nt < 4; nt++) {
                int ct = wc * 4 + nt;
                uint2 bH = *(const uint2*)(bufB + (((ct * 2 + ks) * 2 + 0) * 256) + lane * 8);
                uint2 bL = *(const uint2*)(bufB + (((ct * 2 + ks) * 2 + 1) * 256) + lane * 8);
                #pragma unroll
                for (int mt = 0; mt < 4; mt++) {
                    MMA16816(acc[mt][nt], aH[mt], bH);
                    MMA16816(acc[mt][nt], aH[mt], bL);
                    MMA16816(acc[mt][nt], aL[mt], bH);
                }
            }
        }
    }

    int r0 = by * 128 + wr * 64;
    int c0g = bx * 128 + wc * 32;
    #pragma unroll
    for (int mt = 0; mt < 4; mt++) {
        #pragma unroll
        for (int nt = 0; nt < 4; nt++) {
            int row = r0 + mt * 16 + (lane >> 2);
            int col = c0g + nt * 8 + (lane & 3) * 2;
            int lc = wc * 32 + nt * 8 + (lane & 3) * 2;
            float b0 = sBias[lc], b1 = sBias[lc + 1];
            float2 v0 = {acc[mt][nt][0] + b0, acc[mt][nt][1] + b1};
            float2 v1 = {acc[mt][nt][2] + b0, acc[mt][nt][3] + b1};
            *(float2*)&g_G[(size_t)row * 4096 + col] = v0;
            *(float2*)&g_G[(size_t)(row + 8) * 4096 + col] = v1;
        }
    }
}

// ---------------- persistent HMMA recurrence (R13, converged) ----------------
// 128 CTAs x 512 threads. W resident 128KB. h: 3 x 32KB buffers (chunks 0,1,2
// up front; chunk 3 reuses buf 0). Partials overlay buf 0. Single
// release/acquire grid barrier per step (tid0 poller + BAR).
constexpr int OFF_B = 131072, BCHUNK = 32768;
constexpr int OFF_P = 131072;              // overlay on h buffer 0
constexpr int REC_SMEM = 229376;

__global__ __launch_bounds__(512)
void rec_mma(const float* __restrict__ c_in_l, float* __restrict__ out_c_l,
             float* __restrict__ out_h_l, float* __restrict__ outs, int layer) {
    extern __shared__ char sm[];
    int tid = threadIdx.x, w = tid >> 5, lane = tid & 31;
    int jt = blockIdx.x, m0 = jt * 8;
    uint32_t sb = smem_u32(sm);

    // preload W fragments (resident all timesteps)
    {
        const char* src = (const char*)g_Wp + (size_t)(layer * 128 + jt) * 131072;
        #pragma unroll
        for (int i = 0; i < 16; i++)
            CP16(sb + (uint32_t)(tid + i * 512) * 16, src + (size_t)(tid + i * 512) * 16);
        CP_COMMIT();
        CP_WAIT0();
    }
    __syncthreads();

    int eb = (tid >> 3) & 31, ml = tid & 7, m = m0 + ml;
    float creg = 0.f;
    if (tid < 256) creg = c_in_l[(size_t)eb * MS + m];

    for (int t = 0; t < TS; t++) {
        int pp = t & 1;
        const char* hH = (const char*)g_hf[pp][0];
        const char* hL = (const char*)g_hf[pp][1];

        // G prefetch into registers (read-only during rec; hidden by chunk loop)
        float Gr[4];
        if (tid < 256) {
            #pragma unroll
            for (int g = 0; g < 4; g++)
                Gr[g] = __ldg(&g_G[((size_t)(t * 32 + eb)) * 4096 + g * 1024 + jt * 8 + ml]);
        }

        auto issueH = [&](int c, int buf) {
            uint32_t dst = sb + OFF_B + (uint32_t)buf * BCHUNK;
            const char* sh = hH + (size_t)c * 16384;
            const char* sl = hL + (size_t)c * 16384;
            #pragma unroll
            for (int i = 0; i < 2; i++) {
                uint32_t u16 = (uint32_t)(tid + i * 512) * 16;
                CP16(dst + u16, sh + u16);
                CP16(dst + 16384 + u16, sl + u16);
            }
            CP_COMMIT();
        };

        // all of h(t) is available at step start: issue chunks 0,1,2 up front
        issueH(0, 0);
        issueH(1, 1);
        issueH(2, 2);

        float acc[2][4][4];
        #pragma unroll
        for (int a = 0; a < 2; a++) for (int n = 0; n < 4; n++) for (int q = 0; q < 4; q++)
            acc[a][n][q] = 0.f;

        #pragma unroll
        for (int c = 0; c < 4; c++) {
            if (c == 0)      { CP_WAIT2(); }
            else if (c == 1) { CP_WAIT1(); }
            else if (c == 2) { CP_WAIT1(); }
            else             { CP_WAIT0(); }
            __syncthreads();                   // all threads' chunk-c copies visible
            if (c == 1) issueH(3, 0);          // buf0 free: all threads past chunk0

            int ks = c * 16 + w;
            int buf = (c == 3) ? 0 : c;
            uint32_t abase = (uint32_t)(ks * 2048);
            uint4 aH0 = *(uint4*)(sm + abase +        lane * 16);
            uint4 aL0 = *(uint4*)(sm + abase + 512  + lane * 16);
            uint4 aH1 = *(uint4*)(sm + abase + 1024 + lane * 16);
            uint4 aL1 = *(uint4*)(sm + abase + 1536 + lane * 16);
            uint32_t bbase = (uint32_t)(OFF_B + buf * BCHUNK + w * 1024);
            #pragma unroll
            for (int nt = 0; nt < 4; nt++) {
                uint2 bH = *(uint2*)(sm + bbase + nt * 256 + lane * 8);
                uint2 bL = *(uint2*)(sm + bbase + 16384 + nt * 256 + lane * 8);
                MMA16816(acc[0][nt], aH0, bH);
                MMA16816(acc[0][nt], aH0, bL);
                MMA16816(acc[0][nt], aL0, bH);
                MMA16816(acc[1][nt], aH1, bH);
                MMA16816(acc[1][nt], aH1, bL);
                MMA16816(acc[1][nt], aL1, bH);
            }
        }
        __syncthreads();   // all warps done reading buf0 before partials overlay it

        // two-phase partial staging (overlaid on h buffer 0)
        if (w < 8) {
            #pragma unroll
            for (int mt = 0; mt < 2; mt++)
                #pragma unroll
                for (int nt = 0; nt < 4; nt++) {
                    float4 v = {acc[mt][nt][0], acc[mt][nt][1], acc[mt][nt][2], acc[mt][nt][3]};
                    *(float4*)(sm + OFF_P + (((w * 2 + mt) * 4 + nt) * 32 + lane) * 16) = v;
                }
        }
        __syncthreads();
        if (w >= 8) {
            int ws = w - 8;
            #pragma unroll
            for (int mt = 0; mt < 2; mt++)
                #pragma unroll
                for (int nt = 0; nt < 4; nt++) {
                    float4* p = (float4*)(sm + OFF_P + (((ws * 2 + mt) * 4 + nt) * 32 + lane) * 16);
                    float4 v = *p;
                    v.x += acc[mt][nt][0]; v.y += acc[mt][nt][1];
                    v.z += acc[mt][nt][2]; v.w += acc[mt][nt][3];
                    *p = v;
                }
        }
        __syncthreads();

        if (tid < 256) {
            const float* sPf = (const float*)(sm + OFF_P);
            float gate[4];
            #pragma unroll
            for (int g = 0; g < 4; g++) {
                int jr = g * 8 + ml;
                int mt = jr >> 4, rl = jr & 15;
                int ln = (rl & 7) * 4 + ((eb & 7) >> 1);
                int rg = (rl >> 3) * 2 + (eb & 1);
                int nt = eb >> 3;
                float s = Gr[g];
                #pragma unroll
                for (int ww = 0; ww < 8; ww++)
                    s += sPf[(((ww * 2 + mt) * 4 + nt) * 32 + ln) * 4 + rg];
                gate[g] = s;
            }
            float i_ = 1.f / (1.f + __expf(-gate[0]));
            float f_ = 1.f / (1.f + __expf(-gate[1]));
            float g_ = tanhf(gate[2]);
            float o_ = 1.f / (1.f + __expf(-gate[3]));
            creg = f_ * creg + i_ * g_;
            float hn = o_ * tanhf(creg);

            __nv_bfloat16 hv = __float2bfloat16(hn);
            __nv_bfloat16 lv = __float2bfloat16(hn - __bfloat162float(hv));
            // B-fragment pack for next step
            {
                int ks = m >> 4, kl = m & 15, nt = eb >> 3;
                int ln = (eb & 7) * 4 + ((kl & 7) >> 1);
                int slot = (kl >> 3) * 2 + (kl & 1);
                size_t o = ((size_t)(ks * 4 + nt) * 32 + ln) * 4 + slot;
                g_hf[pp ^ 1][0][o] = hv;
                g_hf[pp ^ 1][1][o] = lv;
            }
            if (layer == 0) {
                // A-fragment pack directly (layer-1 GEMM input)
                int rt = t * 2 + (eb >> 4);
                int rl = eb & 15;
                int ks2 = m >> 4, cl = m & 15;
                int lane2 = (rl & 7) * 4 + ((cl & 7) >> 1);
                int q2 = (rl >> 3) + ((cl >> 3) << 1);
                size_t oA = (((size_t)rt * 64 + ks2) * 2) * 256 + lane2 * 8 + q2 * 2 + (cl & 1);
                g_Af[oA]       = hv;
                g_Af[oA + 256] = lv;
            } else {
                outs[((size_t)eb * TS + t) * MS + m] = hn;
            }
            if (t == TS - 1) out_h_l[(size_t)eb * MS + m] = hn;
        }

        if (t < TS - 1) {   // grid barrier: single release/acquire counter (proven)
            __syncthreads();
            if (tid == 0) {
                unsigned tgt = (unsigned)(t + 1) * gridDim.x;
                asm volatile("red.release.gpu.global.add.u32 [%0], %1;"
                             :: "l"(&g_cnt), "r"(1u) : "memory");
                unsigned v;
                do {
                    asm volatile("ld.acquire.gpu.global.u32 %0, [%1];"
                                 : "=r"(v) : "l"(&g_cnt) : "memory");
                } while (v < tgt);
            }
            __syncthreads();
        }
    }
    if (tid < 256) out_c_l[(size_t)eb * MS + m] = creg;
}

// ------------------------------------------------------------------
extern "C" void kernel_launch(void* const* d_in, const int* in_sizes, int n_in,
                              void* d_out, int out_size) {
    const float* x   = (const float*)d_in[0];
    const float* h   = (const float*)d_in[1];
    const float* c   = (const float*)d_in[2];
    const float* Wih = (const float*)d_in[3];
    const float* Whh = (const float*)d_in[4];
    const float* bih = (const float*)d_in[5];
    const float* bhh = (const float*)d_in[6];

    float* outs  = (float*)d_out;
    float* out_h = outs + (size_t)BS * TS * MS;
    float* out_c = out_h + (size_t)LAY * BS * MS;

    cudaFuncSetAttribute(rec_mma, cudaFuncAttributeMaxDynamicSharedMemorySize, REC_SMEM);
    cudaFuncSetAttribute(gemm_mma, cudaFuncAttributeMaxDynamicSharedMemorySize, GEMM_SMEM);

    conv_w_kernel<<<4096, 256>>>(Whh);
    conv_b_kernel<<<8192, 256>>>(Wih);
    conv_a_kernel<<<4096, 256>>>(x);
    for (int l = 0; l < LAY; l++) {
        gemm_mma<<<dim3(32, 64), 256, GEMM_SMEM>>>(
            l, bih + (size_t)l * JS, bhh + (size_t)l * JS);
        init_hf_kernel<<<(BS * MS + 255) / 256, 256>>>(h + (size_t)l * BS * MS);
        rec_mma<<<128, 512, REC_SMEM>>>(
            c + (size_t)l * BS * MS,
            out_c + (size_t)l * BS * MS,
            out_h + (size_t)l * BS * MS,
            outs, l);
    }
}